// round 8
// baseline (speedup 1.0000x reference)
#include <cuda_runtime.h>

#define CUTOFF 8.0f
#define MAXK 32
#define MAXE (1 << 20)

// Per-edge precompute: (ux, uy, uz, f(|r|)) where u = r/|r|.
__device__ float4 g_edge[MAXE];
// Fallback-path coefficient storage (generic K only).
__device__ float4 g_fc[MAXK];
__device__ float4 g_gc[MAXK];
__device__ int    g_deg;

// ===========================================================================
// Compile-time-K natural cubic spline (uniform knots). All-register Thomas.
// ===========================================================================
template <int K>
__device__ __forceinline__ void build_spline_reg(const float* __restrict__ y,
                                                 float h, float4* sh_out) {
    float yv[K];
#pragma unroll
    for (int i = 0; i < K; i++) yv[i] = y[i];

    const float inv_h = 1.0f / h;
    float dy[K - 1];
#pragma unroll
    for (int i = 0; i < K - 1; i++) dy[i] = (yv[i + 1] - yv[i]) * inv_h;

    constexpr int n = K - 2;
    float M[K];
    M[0] = 0.0f;
    M[K - 1] = 0.0f;
    if (n > 0) {
        float cp[n], dp[n];
        cp[0] = 0.25f;
        dp[0] = 6.0f * (dy[1] - dy[0]) * inv_h * 0.25f;
#pragma unroll
        for (int i = 1; i < n; i++) {
            float rd = 1.0f / (4.0f - cp[i - 1]);
            cp[i] = rd;
            dp[i] = (6.0f * (dy[i + 1] - dy[i]) * inv_h - dp[i - 1]) * rd;
        }
        M[n] = dp[n - 1];
#pragma unroll
        for (int i = n - 2; i >= 0; i--) M[i + 1] = dp[i] - cp[i] * M[i + 2];
    }

    constexpr float SIXTH = 1.0f / 6.0f;
#pragma unroll
    for (int i = 0; i < K - 1; i++) {
        sh_out[i] = make_float4(yv[i],
                                dy[i] - h * (2.0f * M[i] + M[i + 1]) * SIXTH,
                                0.5f * M[i],
                                (M[i + 1] - M[i]) * inv_h * SIXTH);
    }
}

// ===========================================================================
// Kernel 1: per-edge precompute (u = r/|r|, f(|r|)). Pure streaming.
// ===========================================================================
template <int K>
__global__ void __launch_bounds__(256) smeam_edge_kernel(
    const float* __restrict__ r, const float* __restrict__ fy, int E) {
    __shared__ float4 sf[K - 1];
    if (threadIdx.x == 0) build_spline_reg<K>(fy, CUTOFF / (float)(K - 1), sf);
    __syncthreads();

    int i = blockIdx.x * blockDim.x + threadIdx.x;
    if (i >= E) return;

    float x = r[3 * i + 0];
    float y = r[3 * i + 1];
    float z = r[3 * i + 2];
    float d2 = x * x + y * y + z * z;
    float invl = rsqrtf(d2);
    float l = d2 * invl;

    constexpr float hf = CUTOFF / (float)(K - 1);
    constexpr float inv_hf = (float)(K - 1) / CUTOFF;
    int idx = min(max((int)(l * inv_hf), 0), K - 2);
    float s = fmaf((float)idx, -hf, l);
    float4 cf = sf[idx];
    float fv = fmaf(s, fmaf(s, fmaf(s, cf.w, cf.z), cf.y), cf.x);
    g_edge[i] = make_float4(x * invl, y * invl, z * invl, fv);
}

// ===========================================================================
// Kernel 2 (main, persistent gather): single-wave grid (6 blocks/SM via
// launch bounds), grid-stride over e2-groups. Each warp handles a group of
// 4 e2's: the two 16-lane halves each own 2 e2's processed back-to-back.
// Lane l (hl = l&15) gathers partners hl and hl+16. d2 = e2 >> log2(deg)
// when deg is pow2 (no dst load). Block prologue paid once per block.
// ===========================================================================
template <int K>
__global__ void __launch_bounds__(256, 6) smeam_main_gather(
    const int* __restrict__ src, const int* __restrict__ dst,
    const float* __restrict__ gy, float* __restrict__ out, int E) {
    __shared__ float4 sg[K - 1];
    __shared__ int sh_deg, sh_shift;
    if (threadIdx.x == 0) {
        build_spline_reg<K>(gy, 2.0f / (float)(K - 1), sg);
        int N = __ldg(&dst[E - 1]) + 1;
        int deg = E / N;
        sh_deg = deg;
        sh_shift = ((deg & (deg - 1)) == 0) ? (__ffs(deg) - 1) : -1;
    }
    __syncthreads();

    const int deg = sh_deg;
    const int shift = sh_shift;
    const int lane = threadIdx.x & 31;
    const int hl = lane & 15;
    const int grp = lane >> 4;
    const int warp = (blockIdx.x * blockDim.x + threadIdx.x) >> 5;
    const int TW = (gridDim.x * blockDim.x) >> 5;

    constexpr float hg = 2.0f / (float)(K - 1);
    constexpr float inv_hg = (float)(K - 1) * 0.5f;

    if (deg <= 32) {
        const int jh = (hl < deg) ? hl : 0;
        const int jH = (hl + 16 < deg) ? (hl + 16) : jh;
        const bool m0 = hl < deg;
        const bool m1 = hl + 16 < deg;
        const int ngroups = (E + 3) >> 2;

        for (int g = warp; g < ngroups; g += TW) {
            const int e_base = g * 4;
            const int eA_raw = e_base + grp * 2;
            const int eB_raw = eA_raw + 1;
            const bool vA = eA_raw < E;
            const bool vB = eB_raw < E;
            const int eA = vA ? eA_raw : E - 1;
            const int eB = vB ? eB_raw : E - 1;

            // ---- issue all independent loads up front ----
            const int s2A = __ldg(&src[eA]);
            const int s2B = __ldg(&src[eB]);
            const int baseA = s2A * deg;
            const int baseB = s2B * deg;

            float4 u2A = g_edge[eA];             // broadcast within half
            float4 u2B = g_edge[eB];

            float4 PA0 = g_edge[baseA + jh];
            float4 PA1 = g_edge[baseA + jH];
            float4 PB0 = g_edge[baseB + jh];
            float4 PB1 = g_edge[baseB + jH];
            int sA0 = __ldg(&src[baseA + jh]);
            int sA1 = __ldg(&src[baseA + jH]);
            int sB0 = __ldg(&src[baseB + jh]);
            int sB1 = __ldg(&src[baseB + jH]);

            const int d2A = (shift >= 0) ? (eA >> shift) : __ldg(&dst[eA]);
            const int d2B = (shift >= 0) ? (eB >> shift) : __ldg(&dst[eB]);

            // ---- e2 A ----
            float xc, s, gv;
            int idx;
            float4 cf;

            xc = fmaf(-PA0.x, u2A.x, fmaf(-PA0.y, u2A.y, fmaf(-PA0.z, u2A.z, 1.0f)));
            xc = fminf(fmaxf(xc, 0.0f), 2.0f);
            idx = min((int)(xc * inv_hg), K - 2);
            s = fmaf((float)idx, -hg, xc);
            cf = sg[idx];
            gv = fmaf(s, fmaf(s, fmaf(s, cf.w, cf.z), cf.y), cf.x);
            float accA = (m0 && sA0 != d2A) ? PA0.w * gv : 0.0f;

            xc = fmaf(-PA1.x, u2A.x, fmaf(-PA1.y, u2A.y, fmaf(-PA1.z, u2A.z, 1.0f)));
            xc = fminf(fmaxf(xc, 0.0f), 2.0f);
            idx = min((int)(xc * inv_hg), K - 2);
            s = fmaf((float)idx, -hg, xc);
            cf = sg[idx];
            gv = fmaf(s, fmaf(s, fmaf(s, cf.w, cf.z), cf.y), cf.x);
            accA += (m1 && sA1 != d2A) ? PA1.w * gv : 0.0f;

            // ---- e2 B ----
            xc = fmaf(-PB0.x, u2B.x, fmaf(-PB0.y, u2B.y, fmaf(-PB0.z, u2B.z, 1.0f)));
            xc = fminf(fmaxf(xc, 0.0f), 2.0f);
            idx = min((int)(xc * inv_hg), K - 2);
            s = fmaf((float)idx, -hg, xc);
            cf = sg[idx];
            gv = fmaf(s, fmaf(s, fmaf(s, cf.w, cf.z), cf.y), cf.x);
            float accB = (m0 && sB0 != d2B) ? PB0.w * gv : 0.0f;

            xc = fmaf(-PB1.x, u2B.x, fmaf(-PB1.y, u2B.y, fmaf(-PB1.z, u2B.z, 1.0f)));
            xc = fminf(fmaxf(xc, 0.0f), 2.0f);
            idx = min((int)(xc * inv_hg), K - 2);
            s = fmaf((float)idx, -hg, xc);
            cf = sg[idx];
            gv = fmaf(s, fmaf(s, fmaf(s, cf.w, cf.z), cf.y), cf.x);
            accB += (m1 && sB1 != d2B) ? PB1.w * gv : 0.0f;

            // ---- interleaved 16-lane butterflies ----
#pragma unroll
            for (int o = 8; o; o >>= 1) {
                accA += __shfl_xor_sync(0xffffffffu, accA, o);
                accB += __shfl_xor_sync(0xffffffffu, accB, o);
            }
            if (hl == 0) {
                if (vA) out[eA] = accA * u2A.w;
                if (vB) out[eB] = accB * u2B.w;
            }
        }
    } else {
        // deg > 32: one warp per e2, grid-stride, strip-mined partner loop.
        for (int e2 = warp; e2 < E; e2 += TW) {
            float4 u2 = g_edge[e2];
            int s2 = __ldg(&src[e2]);
            int d2v = (shift >= 0) ? (e2 >> shift) : __ldg(&dst[e2]);
            float acc = 0.0f;
            for (int j = lane; j < deg; j += 32) {
                float4 P = g_edge[s2 * deg + j];
                int s1 = __ldg(&src[s2 * deg + j]);
                float xc = fmaf(-P.x, u2.x, fmaf(-P.y, u2.y, fmaf(-P.z, u2.z, 1.0f)));
                xc = fminf(fmaxf(xc, 0.0f), 2.0f);
                int idx = min((int)(xc * inv_hg), K - 2);
                float s = fmaf((float)idx, -hg, xc);
                float4 cf = sg[idx];
                float gv = fmaf(s, fmaf(s, fmaf(s, cf.w, cf.z), cf.y), cf.x);
                acc += (s1 != d2v) ? P.w * gv : 0.0f;
            }
#pragma unroll
            for (int o = 16; o; o >>= 1)
                acc += __shfl_xor_sync(0xffffffffu, acc, o);
            if (lane == 0) out[e2] = acc * u2.w;
        }
    }
}

// ===========================================================================
// Generic-K fallback (runtime K) — correctness-only path.
// ===========================================================================
__device__ void build_spline_rt(const float* y, int K, float h, float4* outc) {
    double dy[MAXK];
    for (int i = 0; i < K - 1; i++) dy[i] = ((double)y[i + 1] - (double)y[i]) / (double)h;
    int n = K - 2;
    double M[MAXK];
    for (int i = 0; i < K; i++) M[i] = 0.0;
    if (n > 0) {
        double cp[MAXK], dp[MAXK];
        double hh = (double)h;
        cp[0] = hh / (4.0 * hh);
        dp[0] = 6.0 * (dy[1] - dy[0]) / (4.0 * hh);
        for (int i = 1; i < n; i++) {
            double denom = 4.0 * hh - hh * cp[i - 1];
            cp[i] = hh / denom;
            dp[i] = (6.0 * (dy[i + 1] - dy[i]) - hh * dp[i - 1]) / denom;
        }
        double x = dp[n - 1];
        M[n] = x;
        for (int i = n - 2; i >= 0; i--) { x = dp[i] - cp[i] * x; M[i + 1] = x; }
    }
    for (int i = 0; i < K - 1; i++) {
        outc[i] = make_float4((float)y[i],
                              (float)(dy[i] - (double)h * (2.0 * M[i] + M[i + 1]) / 6.0),
                              (float)(M[i] / 2.0),
                              (float)((M[i + 1] - M[i]) / (6.0 * (double)h)));
    }
}

__global__ void smeam_build_kernel_rt(const float* fy, const float* gy,
                                      const int* dst, int E, int K) {
    int N = dst[E - 1] + 1;
    g_deg = E / N;
    build_spline_rt(fy, K, CUTOFF / (float)(K - 1), g_fc);
    build_spline_rt(gy, K, 2.0f / (float)(K - 1), g_gc);
}

__global__ void smeam_edge_kernel_rt(const float* __restrict__ r, int E, int K) {
    int i = blockIdx.x * blockDim.x + threadIdx.x;
    if (i >= E) return;
    float x = r[3 * i + 0], y = r[3 * i + 1], z = r[3 * i + 2];
    float d2 = x * x + y * y + z * z;
    float invl = rsqrtf(d2);
    float l = d2 * invl;
    float hf = CUTOFF / (float)(K - 1);
    float inv_hf = (float)(K - 1) / CUTOFF;
    int idx = min(max((int)floorf(l * inv_hf), 0), K - 2);
    float s = l - (float)idx * hf;
    float4 cf = g_fc[idx];
    g_edge[i] = make_float4(x * invl, y * invl, z * invl,
                            cf.x + s * (cf.y + s * (cf.z + s * cf.w)));
}

__global__ void smeam_main_kernel_rt(const int* __restrict__ src,
                                     const int* __restrict__ dst,
                                     float* __restrict__ out, int E, int K) {
    int warp = (blockIdx.x * blockDim.x + threadIdx.x) >> 5;
    int lane = threadIdx.x & 31;
    if (warp >= E) return;
    int e2 = warp;
    float4 u2 = g_edge[e2];
    int s2 = src[e2], d2 = dst[e2];
    int deg = g_deg;
    float hg = 2.0f / (float)(K - 1);
    float inv_hg = (float)(K - 1) * 0.5f;
    float acc = 0.0f;
    for (int j = lane; j < deg; j += 32) {
        int e1 = s2 * deg + j;
        float4 u1 = g_edge[e1];
        int s1 = src[e1];
        float c = -(u1.x * u2.x + u1.y * u2.y + u1.z * u2.z);
        c = fminf(fmaxf(c, -1.0f), 1.0f);
        float xc = c + 1.0f;
        int idx = min(max((int)floorf(xc * inv_hg), 0), K - 2);
        float s = xc - (float)idx * hg;
        float4 cf = g_gc[idx];
        float gv = cf.x + s * (cf.y + s * (cf.z + s * cf.w));
        acc += (s1 != d2) ? u1.w * u2.w * gv : 0.0f;
    }
#pragma unroll
    for (int o = 16; o; o >>= 1) acc += __shfl_down_sync(0xffffffffu, acc, o);
    if (lane == 0) out[e2] = acc;
}

// ===========================================================================
template <int K>
static void launch_ct(const float* r, const float* fy, const float* gy,
                      const int* src, const int* dst, float* out, int E) {
    const int t = 256;
    smeam_edge_kernel<K><<<(E + t - 1) / t, t>>>(r, fy, E);
    // Single-wave persistent grid: 6 blocks/SM (forced by launch bounds)
    // x 148 SMs = 888 blocks. Grid-stride inside covers any deg / E.
    int need_warps = (E + 3) / 4;               // deg<=32 path demand
    int need_blocks = (need_warps * 32 + t - 1) / t;
    int blocks = 888;
    if (need_blocks < blocks) blocks = need_blocks;
    if (blocks < 1) blocks = 1;
    smeam_main_gather<K><<<blocks, t>>>(src, dst, gy, out, E);
}

extern "C" void kernel_launch(void* const* d_in, const int* in_sizes, int n_in,
                              void* d_out, int out_size) {
    const float* r   = (const float*)d_in[0];
    const float* fy  = (const float*)d_in[1];
    const float* gy  = (const float*)d_in[2];
    const int*   src = (const int*)d_in[3];
    const int*   dst = (const int*)d_in[4];
    float*       out = (float*)d_out;

    int E = in_sizes[3];
    int K = in_sizes[1];

    switch (K) {
        case 3: launch_ct<3>(r, fy, gy, src, dst, out, E); break;
        case 4: launch_ct<4>(r, fy, gy, src, dst, out, E); break;
        case 5: launch_ct<5>(r, fy, gy, src, dst, out, E); break;
        case 6: launch_ct<6>(r, fy, gy, src, dst, out, E); break;
        case 7: launch_ct<7>(r, fy, gy, src, dst, out, E); break;
        case 8: launch_ct<8>(r, fy, gy, src, dst, out, E); break;
        case 9: launch_ct<9>(r, fy, gy, src, dst, out, E); break;
        default: {
            smeam_build_kernel_rt<<<1, 1>>>(fy, gy, dst, E, K);
            int t = 256;
            smeam_edge_kernel_rt<<<(E + t - 1) / t, t>>>(r, E, K);
            long total = (long)E * 32;
            unsigned blocks = (unsigned)((total + t - 1) / t);
            smeam_main_kernel_rt<<<blocks, t>>>(src, dst, out, E, K);
            break;
        }
    }
}

// round 9
// speedup vs baseline: 1.1145x; 1.1145x over previous
#include <cuda_runtime.h>

#define CUTOFF 8.0f
#define MAXK 32
#define MAXE (1 << 20)

// Per-edge precompute: (ux*SC, uy*SC, uz*SC, f(|r|)) where u = r/|r| and
// SC = sqrt((K-1)/2) so that dot of two table vectors = inv_hg * cos.
__device__ float4 g_edge[MAXE];
// Fallback-path coefficient storage (generic K only).
__device__ float4 g_fc[MAXK];
__device__ float4 g_gc[MAXK];
__device__ int    g_deg;

// ===========================================================================
// Compile-time-K natural cubic spline (uniform knots). All-register Thomas.
// ===========================================================================
template <int K>
__device__ __forceinline__ void build_spline_reg(const float* __restrict__ y,
                                                 float h, float4* sh_out) {
    float yv[K];
#pragma unroll
    for (int i = 0; i < K; i++) yv[i] = y[i];

    const float inv_h = 1.0f / h;
    float dy[K - 1];
#pragma unroll
    for (int i = 0; i < K - 1; i++) dy[i] = (yv[i + 1] - yv[i]) * inv_h;

    constexpr int n = K - 2;
    float M[K];
    M[0] = 0.0f;
    M[K - 1] = 0.0f;
    if (n > 0) {
        float cp[n], dp[n];
        cp[0] = 0.25f;
        dp[0] = 6.0f * (dy[1] - dy[0]) * inv_h * 0.25f;
#pragma unroll
        for (int i = 1; i < n; i++) {
            float rd = 1.0f / (4.0f - cp[i - 1]);
            cp[i] = rd;
            dp[i] = (6.0f * (dy[i + 1] - dy[i]) * inv_h - dp[i - 1]) * rd;
        }
        M[n] = dp[n - 1];
#pragma unroll
        for (int i = n - 2; i >= 0; i--) M[i + 1] = dp[i] - cp[i] * M[i + 2];
    }

    constexpr float SIXTH = 1.0f / 6.0f;
#pragma unroll
    for (int i = 0; i < K - 1; i++) {
        sh_out[i] = make_float4(yv[i],
                                dy[i] - h * (2.0f * M[i] + M[i + 1]) * SIXTH,
                                0.5f * M[i],
                                (M[i + 1] - M[i]) * inv_h * SIXTH);
    }
}

// ===========================================================================
// Kernel 1: per-edge precompute. Writes SCALED unit vector + f(|r|).
// ===========================================================================
template <int K>
__global__ void __launch_bounds__(256) smeam_edge_kernel(
    const float* __restrict__ r, const float* __restrict__ fy, int E) {
    __shared__ float4 sf[K - 1];
    if (threadIdx.x == 0) build_spline_reg<K>(fy, CUTOFF / (float)(K - 1), sf);
    __syncthreads();

    int i = blockIdx.x * blockDim.x + threadIdx.x;
    if (i >= E) return;

    float x = r[3 * i + 0];
    float y = r[3 * i + 1];
    float z = r[3 * i + 2];
    float d2 = x * x + y * y + z * z;
    float invl = rsqrtf(d2);
    float l = d2 * invl;

    constexpr float hf = CUTOFF / (float)(K - 1);
    constexpr float inv_hf = (float)(K - 1) / CUTOFF;
    int idx = min(max((int)(l * inv_hf), 0), K - 2);
    float s = fmaf((float)idx, -hf, l);
    float4 cf = sf[idx];
    float fv = fmaf(s, fmaf(s, fmaf(s, cf.w, cf.z), cf.y), cf.x);

    const float SC = sqrtf((float)(K - 1) * 0.5f);  // sqrt(inv_hg)
    float sl = invl * SC;
    g_edge[i] = make_float4(x * sl, y * sl, z * sl, fv);
}

// ===========================================================================
// g-spline eval on scaled vectors + unit-interval coefficients.
// t = inv_hg*(1 - cos) comes straight out of the FFMA dot chain.
// ===========================================================================
template <int K>
__device__ __forceinline__ float eval_g(float4 P, float4 u2, int s1, int d2,
                                        const float4* __restrict__ sg,
                                        float acc) {
    constexpr float inv_hg = (float)(K - 1) * 0.5f;
    float t = fmaf(-P.x, u2.x, fmaf(-P.y, u2.y, fmaf(-P.z, u2.z, inv_hg)));
    int idx = min((int)t, K - 2);        // trunc: tiny-negative t -> 0
    float s = t - (float)idx;
    float4 cf = sg[idx];
    float gv = fmaf(s, fmaf(s, fmaf(s, cf.w, cf.z), cf.y), cf.x);
    if (s1 != d2) acc = fmaf(P.w, gv, acc);
    return acc;
}

// ===========================================================================
// Group worker: full groups of 4 e2 (2 per 16-lane half) + scalar tail.
// FULL=true specializes deg==32 (no lane masks).
// ===========================================================================
template <int K, bool FULL>
__device__ __forceinline__ void do_groups(
    const int* __restrict__ src, const int* __restrict__ dst,
    float* __restrict__ out, const float4* __restrict__ sg,
    int E, int deg, int shift, int warp, int TW, int hl, int grp) {
    const int jh = FULL ? hl : ((hl < deg) ? hl : 0);
    const int jH = FULL ? (hl + 16) : ((hl + 16 < deg) ? (hl + 16) : 0);
    const bool m0 = FULL || (hl < deg);
    const bool m1 = FULL || (hl + 16 < deg);
    const int ng = E >> 2;   // full groups

    for (int g = warp; g < ng; g += TW) {
        const int eA = g * 4 + grp * 2;

        int2 s2 = *reinterpret_cast<const int2*>(src + eA);
        const int baseA = s2.x * deg;
        const int baseB = s2.y * deg;

        float4 u2A = g_edge[eA];
        float4 u2B = g_edge[eA + 1];

        float4 PA0 = g_edge[baseA + jh];
        float4 PA1 = g_edge[baseA + jH];
        float4 PB0 = g_edge[baseB + jh];
        float4 PB1 = g_edge[baseB + jH];
        int sA0 = __ldg(src + baseA + jh);
        int sA1 = __ldg(src + baseA + jH);
        int sB0 = __ldg(src + baseB + jh);
        int sB1 = __ldg(src + baseB + jH);

        if (!FULL) {
            if (!m0) { PA0.w = 0.0f; PB0.w = 0.0f; }
            if (!m1) { PA1.w = 0.0f; PB1.w = 0.0f; }
        }

        int d2A, d2B;
        if (shift >= 0) {
            d2A = eA >> shift;
            d2B = (eA + 1) >> shift;
        } else {
            int2 dd = *reinterpret_cast<const int2*>(dst + eA);
            d2A = dd.x; d2B = dd.y;
        }

        float accA = 0.0f, accB = 0.0f;
        accA = eval_g<K>(PA0, u2A, sA0, d2A, sg, accA);
        accA = eval_g<K>(PA1, u2A, sA1, d2A, sg, accA);
        accB = eval_g<K>(PB0, u2B, sB0, d2B, sg, accB);
        accB = eval_g<K>(PB1, u2B, sB1, d2B, sg, accB);

#pragma unroll
        for (int o = 8; o; o >>= 1) {
            accA += __shfl_xor_sync(0xffffffffu, accA, o);
            accB += __shfl_xor_sync(0xffffffffu, accB, o);
        }
        if (hl == 0) {
            *reinterpret_cast<float2*>(out + eA) =
                make_float2(accA * u2A.w, accB * u2B.w);
        }
    }

    // tail: remaining e2 in [E&~3, E), at most 3. Both halves compute the
    // same e2 redundantly; reduce within half; lane 0 stores.
    {
        int e2 = (E & ~3) + warp;
        if (e2 < E) {
            float4 u2 = g_edge[e2];
            int s2v = __ldg(src + e2);
            int base = s2v * deg;
            float4 P0 = g_edge[base + jh];
            float4 P1 = g_edge[base + jH];
            int s0 = __ldg(src + base + jh);
            int s1v = __ldg(src + base + jH);
            if (!m0) P0.w = 0.0f;
            if (!m1) P1.w = 0.0f;
            int d2 = (shift >= 0) ? (e2 >> shift) : __ldg(dst + e2);
            float acc = 0.0f;
            acc = eval_g<K>(P0, u2, s0, d2, sg, acc);
            acc = eval_g<K>(P1, u2, s1v, d2, sg, acc);
#pragma unroll
            for (int o = 8; o; o >>= 1)
                acc += __shfl_xor_sync(0xffffffffu, acc, o);
            if (hl == 0 && grp == 0) out[e2] = acc * u2.w;
        }
    }
}

// ===========================================================================
// Kernel 2 (main, persistent gather): single-wave grid, grid-stride groups.
// ===========================================================================
template <int K>
__global__ void __launch_bounds__(256) smeam_main_gather(
    const int* __restrict__ src, const int* __restrict__ dst,
    const float* __restrict__ gy, float* __restrict__ out, int E) {
    __shared__ float4 sg[K - 1];
    __shared__ int sh_deg, sh_shift;
    if (threadIdx.x == 0) {
        build_spline_reg<K>(gy, 2.0f / (float)(K - 1), sg);
        // rescale to unit-interval parameter: value = a + s(b*h + s(c*h^2 + s d*h^3))
        constexpr float hg = 2.0f / (float)(K - 1);
#pragma unroll
        for (int i = 0; i < K - 1; i++) {
            float4 c = sg[i];
            sg[i] = make_float4(c.x, c.y * hg, c.z * hg * hg, c.w * hg * hg * hg);
        }
        int N = __ldg(&dst[E - 1]) + 1;
        int deg = E / N;
        sh_deg = deg;
        sh_shift = ((deg & (deg - 1)) == 0) ? (__ffs(deg) - 1) : -1;
    }
    __syncthreads();

    const int deg = sh_deg;
    const int shift = sh_shift;
    const int lane = threadIdx.x & 31;
    const int hl = lane & 15;
    const int grp = lane >> 4;
    const int warp = (blockIdx.x * blockDim.x + threadIdx.x) >> 5;
    const int TW = (gridDim.x * blockDim.x) >> 5;

    if (deg == 32) {
        do_groups<K, true>(src, dst, out, sg, E, deg, shift, warp, TW, hl, grp);
    } else if (deg <= 32) {
        do_groups<K, false>(src, dst, out, sg, E, deg, shift, warp, TW, hl, grp);
    } else {
        // deg > 32: one warp per e2, grid-stride, strip-mined partner loop.
        for (int e2 = warp; e2 < E; e2 += TW) {
            float4 u2 = g_edge[e2];
            int s2 = __ldg(&src[e2]);
            int d2v = (shift >= 0) ? (e2 >> shift) : __ldg(&dst[e2]);
            float acc = 0.0f;
            for (int j = lane; j < deg; j += 32) {
                float4 P = g_edge[s2 * deg + j];
                int s1 = __ldg(&src[s2 * deg + j]);
                acc = eval_g<K>(P, u2, s1, d2v, sg, acc);
            }
#pragma unroll
            for (int o = 16; o; o >>= 1)
                acc += __shfl_xor_sync(0xffffffffu, acc, o);
            if (lane == 0) out[e2] = acc * u2.w;
        }
    }
}

// ===========================================================================
// Generic-K fallback (runtime K) — correctness-only path (unscaled table).
// ===========================================================================
__device__ void build_spline_rt(const float* y, int K, float h, float4* outc) {
    double dy[MAXK];
    for (int i = 0; i < K - 1; i++) dy[i] = ((double)y[i + 1] - (double)y[i]) / (double)h;
    int n = K - 2;
    double M[MAXK];
    for (int i = 0; i < K; i++) M[i] = 0.0;
    if (n > 0) {
        double cp[MAXK], dp[MAXK];
        double hh = (double)h;
        cp[0] = hh / (4.0 * hh);
        dp[0] = 6.0 * (dy[1] - dy[0]) / (4.0 * hh);
        for (int i = 1; i < n; i++) {
            double denom = 4.0 * hh - hh * cp[i - 1];
            cp[i] = hh / denom;
            dp[i] = (6.0 * (dy[i + 1] - dy[i]) - hh * dp[i - 1]) / denom;
        }
        double x = dp[n - 1];
        M[n] = x;
        for (int i = n - 2; i >= 0; i--) { x = dp[i] - cp[i] * x; M[i + 1] = x; }
    }
    for (int i = 0; i < K - 1; i++) {
        outc[i] = make_float4((float)y[i],
                              (float)(dy[i] - (double)h * (2.0 * M[i] + M[i + 1]) / 6.0),
                              (float)(M[i] / 2.0),
                              (float)((M[i + 1] - M[i]) / (6.0 * (double)h)));
    }
}

__global__ void smeam_build_kernel_rt(const float* fy, const float* gy,
                                      const int* dst, int E, int K) {
    int N = dst[E - 1] + 1;
    g_deg = E / N;
    build_spline_rt(fy, K, CUTOFF / (float)(K - 1), g_fc);
    build_spline_rt(gy, K, 2.0f / (float)(K - 1), g_gc);
}

__global__ void smeam_edge_kernel_rt(const float* __restrict__ r, int E, int K) {
    int i = blockIdx.x * blockDim.x + threadIdx.x;
    if (i >= E) return;
    float x = r[3 * i + 0], y = r[3 * i + 1], z = r[3 * i + 2];
    float d2 = x * x + y * y + z * z;
    float invl = rsqrtf(d2);
    float l = d2 * invl;
    float hf = CUTOFF / (float)(K - 1);
    float inv_hf = (float)(K - 1) / CUTOFF;
    int idx = min(max((int)floorf(l * inv_hf), 0), K - 2);
    float s = l - (float)idx * hf;
    float4 cf = g_fc[idx];
    g_edge[i] = make_float4(x * invl, y * invl, z * invl,
                            cf.x + s * (cf.y + s * (cf.z + s * cf.w)));
}

__global__ void smeam_main_kernel_rt(const int* __restrict__ src,
                                     const int* __restrict__ dst,
                                     float* __restrict__ out, int E, int K) {
    int warp = (blockIdx.x * blockDim.x + threadIdx.x) >> 5;
    int lane = threadIdx.x & 31;
    if (warp >= E) return;
    int e2 = warp;
    float4 u2 = g_edge[e2];
    int s2 = src[e2], d2 = dst[e2];
    int deg = g_deg;
    float hg = 2.0f / (float)(K - 1);
    float inv_hg = (float)(K - 1) * 0.5f;
    float acc = 0.0f;
    for (int j = lane; j < deg; j += 32) {
        int e1 = s2 * deg + j;
        float4 u1 = g_edge[e1];
        int s1 = src[e1];
        float c = -(u1.x * u2.x + u1.y * u2.y + u1.z * u2.z);
        c = fminf(fmaxf(c, -1.0f), 1.0f);
        float xc = c + 1.0f;
        int idx = min(max((int)floorf(xc * inv_hg), 0), K - 2);
        float s = xc - (float)idx * hg;
        float4 cf = g_gc[idx];
        float gv = cf.x + s * (cf.y + s * (cf.z + s * cf.w));
        acc += (s1 != d2) ? u1.w * u2.w * gv : 0.0f;
    }
#pragma unroll
    for (int o = 16; o; o >>= 1) acc += __shfl_down_sync(0xffffffffu, acc, o);
    if (lane == 0) out[e2] = acc;
}

// ===========================================================================
template <int K>
static void launch_ct(const float* r, const float* fy, const float* gy,
                      const int* src, const int* dst, float* out, int E) {
    const int t = 256;
    smeam_edge_kernel<K><<<(E + t - 1) / t, t>>>(r, fy, E);
    // Single-wave persistent grid: ~5 resident blocks/SM at natural regs
    // x 148 SMs = 740 blocks. Grid-stride inside covers any deg / E.
    int need_warps = (E + 3) / 4;               // deg<=32 path demand
    int need_blocks = (need_warps * 32 + t - 1) / t;
    int blocks = 740;
    if (need_blocks < blocks) blocks = need_blocks;
    if (blocks < 1) blocks = 1;
    smeam_main_gather<K><<<blocks, t>>>(src, dst, gy, out, E);
}

extern "C" void kernel_launch(void* const* d_in, const int* in_sizes, int n_in,
                              void* d_out, int out_size) {
    const float* r   = (const float*)d_in[0];
    const float* fy  = (const float*)d_in[1];
    const float* gy  = (const float*)d_in[2];
    const int*   src = (const int*)d_in[3];
    const int*   dst = (const int*)d_in[4];
    float*       out = (float*)d_out;

    int E = in_sizes[3];
    int K = in_sizes[1];

    switch (K) {
        case 3: launch_ct<3>(r, fy, gy, src, dst, out, E); break;
        case 4: launch_ct<4>(r, fy, gy, src, dst, out, E); break;
        case 5: launch_ct<5>(r, fy, gy, src, dst, out, E); break;
        case 6: launch_ct<6>(r, fy, gy, src, dst, out, E); break;
        case 7: launch_ct<7>(r, fy, gy, src, dst, out, E); break;
        case 8: launch_ct<8>(r, fy, gy, src, dst, out, E); break;
        case 9: launch_ct<9>(r, fy, gy, src, dst, out, E); break;
        default: {
            smeam_build_kernel_rt<<<1, 1>>>(fy, gy, dst, E, K);
            int t = 256;
            smeam_edge_kernel_rt<<<(E + t - 1) / t, t>>>(r, E, K);
            long total = (long)E * 32;
            unsigned blocks = (unsigned)((total + t - 1) / t);
            smeam_main_kernel_rt<<<blocks, t>>>(src, dst, out, E, K);
            break;
        }
    }
}